// round 1
// baseline (speedup 1.0000x reference)
#include <cuda_runtime.h>
#include <math.h>

// Problem constants (fixed shapes from reference)
#define BB 16
#define CC 1024
#define DD 768
#define TAU_INV 10.0f
#define KHARD 306      // int((C-1)*0.3)
#define KRAND 717      // (C-1) - KHARD
#define SLOTS_PER_B 128
#define MAXP (BB * SLOTS_PER_B)   // 2048
#define ATILE 32
#define ETILE 128
#define KTILE 32

// Static device scratch (zero-initialized at module load; rows for unused
// slots are never written, so they stay 0 deterministically across replays).
__device__ float g_pnorm[CC * DD];           // normalized prototypes  (3 MB)
__device__ float g_F[MAXP * DD];             // normalized positive-anchor feats (6.3 MB)
__device__ float g_S[MAXP * CC];             // raw similarities per anchor (8.4 MB)
__device__ int   g_posList[MAXP];            // column index c per slot
__device__ int   g_posCount[BB];
__device__ unsigned char g_randFlag[BB * CC];
__device__ float g_term[MAXP];

__device__ __forceinline__ float neg_inf() { return __int_as_float(0xff800000); }

// ---------------------------------------------------------------------------
// Kernel 0: normalize label_proto rows -> g_pnorm
// ---------------------------------------------------------------------------
__global__ void k_prep_p(const float* __restrict__ p) {
    int e = blockIdx.x;
    const float* row = p + e * DD;
    float ss = 0.f;
    for (int k = threadIdx.x; k < DD; k += 256) { float v = row[k]; ss += v * v; }
    // block reduce sum
    for (int o = 16; o > 0; o >>= 1) ss += __shfl_xor_sync(0xffffffffu, ss, o);
    __shared__ float sW[8];
    __shared__ float sInv;
    if ((threadIdx.x & 31) == 0) sW[threadIdx.x >> 5] = ss;
    __syncthreads();
    if (threadIdx.x == 0) {
        float t = 0.f;
        for (int w = 0; w < 8; w++) t += sW[w];
        sInv = 1.0f / fmaxf(sqrtf(t), 1e-12f);
    }
    __syncthreads();
    float inv = sInv;
    for (int k = threadIdx.x; k < DD; k += 256) g_pnorm[e * DD + k] = row[k] * inv;
}

// ---------------------------------------------------------------------------
// Kernel 1: per batch element b (16 blocks, 256 threads):
//  - positive count + deterministic compaction into 128 slots
//  - random-negative set: exact top-KRAND of masked rand_scores
//    (binary search on float bit pattern; ties -> lowest indices, matching
//     jax.lax.top_k)
// ---------------------------------------------------------------------------
__global__ void k_batch(const int* __restrict__ targets, const float* __restrict__ rsc) {
    int b = blockIdx.x, tid = threadIdx.x;
    __shared__ unsigned int skey[CC];
    __shared__ unsigned char sfl[CC];
    __shared__ int sW[8];
    __shared__ int sOut;

    int lane = tid & 31, wid = tid >> 5;
    int e0 = tid * 4;
    unsigned int key[4]; int posf[4]; int cnt = 0;
#pragma unroll
    for (int j = 0; j < 4; j++) {
        int e = e0 + j;
        int isPos = (targets[b * CC + e] != 0);
        posf[j] = isPos; cnt += isPos;
        // rand_scores in [0,1): float bits are order-preserving as uint; +1 so
        // masked (positive) columns at key 0 are strictly below any real score.
        unsigned int k = isPos ? 0u : (__float_as_uint(rsc[b * CC + e]) + 1u);
        key[j] = k; skey[e] = k;
    }
    // exclusive prefix scan of positive counts (deterministic compaction)
    int inc = cnt;
    for (int o = 1; o < 32; o <<= 1) {
        int v = __shfl_up_sync(0xffffffffu, inc, o);
        if (lane >= o) inc += v;
    }
    if (lane == 31) sW[wid] = inc;
    __syncthreads();
    if (tid == 0) {
        int acc = 0;
        for (int w = 0; w < 8; w++) { int v = sW[w]; sW[w] = acc; acc += v; }
        g_posCount[b] = acc;
    }
    __syncthreads();
    int rank = sW[wid] + inc - cnt;
#pragma unroll
    for (int j = 0; j < 4; j++) {
        if (posf[j]) {
            if (rank < SLOTS_PER_B) g_posList[b * SLOTS_PER_B + rank] = e0 + j;
            rank++;
        }
    }
    __syncthreads();

    // binary search: largest V with count(key >= V) >= KRAND
    unsigned lo = 0u, hi = 0xFFFFFFFFu;
    while (hi - lo > 1u) {
        unsigned mid = lo + ((hi - lo) >> 1);
        int c4 = 0;
#pragma unroll
        for (int j = 0; j < 4; j++) c4 += (key[j] >= mid);
        for (int o = 16; o > 0; o >>= 1) c4 += __shfl_xor_sync(0xffffffffu, c4, o);
        if (lane == 0) sW[wid] = c4;
        __syncthreads();
        if (tid == 0) { int t = 0; for (int w = 0; w < 8; w++) t += sW[w]; sOut = t; }
        __syncthreads();
        int total = sOut;
        __syncthreads();
        if (total >= KRAND) lo = mid; else hi = mid;
    }
    unsigned V = lo;
    int both4 = 0;
#pragma unroll
    for (int j = 0; j < 4; j++) both4 += (key[j] > V) * 2048 + (key[j] == V);
    for (int o = 16; o > 0; o >>= 1) both4 += __shfl_xor_sync(0xffffffffu, both4, o);
    if (lane == 0) sW[wid] = both4;
    __syncthreads();
    if (tid == 0) { int t = 0; for (int w = 0; w < 8; w++) t += sW[w]; sOut = t; }
    __syncthreads();
    int n_gt = sOut / 2048;
    int n_eq = sOut % 2048;
    int rrem = KRAND - n_gt;   // >= 1 by construction

    if (n_eq == rrem) {
        // all elements equal to V are selected (common case)
#pragma unroll
        for (int j = 0; j < 4; j++) sfl[e0 + j] = (key[j] >= V) ? 1 : 0;
        __syncthreads();
    } else {
        // rare: duplicates straddle the boundary -> lowest indices win
#pragma unroll
        for (int j = 0; j < 4; j++) sfl[e0 + j] = (key[j] > V) ? 1 : 0;
        __syncthreads();
        if (tid == 0) {
            int rem = rrem;
            for (int e = 0; e < CC && rem > 0; e++)
                if (skey[e] == V) { sfl[e] = 1; rem--; }
        }
        __syncthreads();
    }
#pragma unroll
    for (int j = 0; j < 4; j++) g_randFlag[b * CC + e0 + j] = sfl[e0 + j];
}

// ---------------------------------------------------------------------------
// Kernel 1b: gather + normalize positive anchor features -> g_F
// ---------------------------------------------------------------------------
__global__ void k_norm_f(const float* __restrict__ f) {
    int i = blockIdx.x;
    int b = i >> 7, r = i & 127;
    int cnt = g_posCount[b]; if (cnt > SLOTS_PER_B) cnt = SLOTS_PER_B;
    if (r >= cnt) return;
    int c = g_posList[i];
    const float* src = f + (size_t)(b * CC + c) * DD;
    float ss = 0.f;
    for (int k = threadIdx.x; k < DD; k += 128) { float v = src[k]; ss += v * v; }
    for (int o = 16; o > 0; o >>= 1) ss += __shfl_xor_sync(0xffffffffu, ss, o);
    __shared__ float sW[4];
    __shared__ float sInv;
    if ((threadIdx.x & 31) == 0) sW[threadIdx.x >> 5] = ss;
    __syncthreads();
    if (threadIdx.x == 0) {
        float t = sW[0] + sW[1] + sW[2] + sW[3];
        sInv = 1.0f / fmaxf(sqrtf(t), 1e-12f);
    }
    __syncthreads();
    float inv = sInv;
    for (int k = threadIdx.x; k < DD; k += 128) g_F[i * DD + k] = src[k] * inv;
}

// ---------------------------------------------------------------------------
// Kernel 2: tiled fp32 GEMM  S[slot][e] = dot(F[slot], Pn[e])
// grid (MAXP/ATILE=64, CC/ETILE=8), 256 threads, 4x4 register tile/thread
// ---------------------------------------------------------------------------
__global__ void k_gemm() {
    int aBase = blockIdx.x * ATILE;
    int b = aBase >> 7;
    int cnt = g_posCount[b]; if (cnt > SLOTS_PER_B) cnt = SLOTS_PER_B;
    if ((aBase & 127) >= cnt) return;
    int eBase = blockIdx.y * ETILE;

    __shared__ float fT[ATILE][KTILE + 1];
    __shared__ float pT[ETILE][KTILE + 1];
    int tid = threadIdx.x, tx = tid & 31, ty = tid >> 5;
    float acc[4][4] = {};

    for (int k0 = 0; k0 < DD; k0 += KTILE) {
        int kk = tid & 31, row = tid >> 5;
#pragma unroll
        for (int i = 0; i < 4; i++)
            fT[row + 8 * i][kk] = g_F[(aBase + row + 8 * i) * DD + k0 + kk];
#pragma unroll
        for (int i = 0; i < 16; i++)
            pT[row + 8 * i][kk] = g_pnorm[(eBase + row + 8 * i) * DD + k0 + kk];
        __syncthreads();
#pragma unroll
        for (int k = 0; k < KTILE; k++) {
            float av[4], bv[4];
#pragma unroll
            for (int j = 0; j < 4; j++) av[j] = fT[ty * 4 + j][k];   // broadcast
#pragma unroll
            for (int j = 0; j < 4; j++) bv[j] = pT[tx + 32 * j][k];  // conflict-free
#pragma unroll
            for (int ia = 0; ia < 4; ia++)
#pragma unroll
                for (int jb = 0; jb < 4; jb++)
                    acc[ia][jb] = fmaf(av[ia], bv[jb], acc[ia][jb]);
        }
        __syncthreads();
    }
#pragma unroll
    for (int ia = 0; ia < 4; ia++) {
        int slot = aBase + ty * 4 + ia;
        if ((slot & 127) < cnt) {
#pragma unroll
            for (int jb = 0; jb < 4; jb++)
                g_S[slot * CC + eBase + tx + 32 * jb] = acc[ia][jb];
        }
    }
}

// ---------------------------------------------------------------------------
// Kernel 3: per positive anchor: hard top-KHARD values (bitonic sort over
// negatives), + random-set exp sum, -> per-anchor loss term
// ---------------------------------------------------------------------------
__global__ void k_select(const int* __restrict__ targets) {
    int i = blockIdx.x;
    int b = i >> 7, r = i & 127;
    int cnt = g_posCount[b]; if (cnt > SLOTS_PER_B) cnt = SLOTS_PER_B;
    int tid = threadIdx.x;
    if (r >= cnt) { if (tid == 0) g_term[i] = 0.f; return; }
    int c = g_posList[i];

    __shared__ float sv[CC];
    __shared__ float sWf[8];
    __shared__ float sBc;

    float s[4]; int neg[4];
#pragma unroll
    for (int j = 0; j < 4; j++) {
        int e = tid + 256 * j;
        s[j] = g_S[i * CC + e];
        neg[j] = (targets[b * CC + e] == 0);
    }
    // max over negatives (upper bound for all selected values)
    float m = neg_inf();
#pragma unroll
    for (int j = 0; j < 4; j++) if (neg[j]) m = fmaxf(m, s[j]);
    for (int o = 16; o > 0; o >>= 1) m = fmaxf(m, __shfl_xor_sync(0xffffffffu, m, o));
    if ((tid & 31) == 0) sWf[tid >> 5] = m;
    __syncthreads();
    if (tid == 0) {
        float t = sWf[0];
        for (int w = 1; w < 8; w++) t = fmaxf(t, sWf[w]);
        sBc = t;
    }
    __syncthreads();
    float M = sBc;

    // random-negative exp sum (indices shared per batch)
    float rs = 0.f;
#pragma unroll
    for (int j = 0; j < 4; j++) {
        int e = tid + 256 * j;
        if (g_randFlag[b * CC + e]) rs += __expf((s[j] - M) * TAU_INV);
    }
    // stage negatives for sort (positives -> -inf)
#pragma unroll
    for (int j = 0; j < 4; j++) {
        int e = tid + 256 * j;
        sv[e] = neg[j] ? s[j] : neg_inf();
    }
    __syncthreads();

    // bitonic sort ascending over 1024 elements
    for (unsigned k = 2; k <= CC; k <<= 1) {
        for (unsigned jj = k >> 1; jj > 0; jj >>= 1) {
            for (int t = tid; t < CC; t += 256) {
                int ixj = t ^ (int)jj;
                if (ixj > t) {
                    float a = sv[t], bb2 = sv[ixj];
                    bool asc = ((t & k) == 0);
                    if (asc ? (a > bb2) : (a < bb2)) { sv[t] = bb2; sv[ixj] = a; }
                }
            }
            __syncthreads();
        }
    }
    // hard negatives = top KHARD = last KHARD entries
    float hs = 0.f;
    for (int t = CC - KHARD + tid; t < CC; t += 256)
        hs += __expf((sv[t] - M) * TAU_INV);

    float tot = rs + hs;
    for (int o = 16; o > 0; o >>= 1) tot += __shfl_xor_sync(0xffffffffu, tot, o);
    if ((tid & 31) == 0) sWf[tid >> 5] = tot;
    __syncthreads();
    if (tid == 0) {
        float su = 0.f;
        for (int w = 0; w < 8; w++) su += sWf[w];
        float pos = g_S[i * CC + c] * TAU_INV;
        float lse = M * TAU_INV + __logf(su);
        float d = lse - pos;  // term = logaddexp(pos,lse) - pos
        float term = (d > 0.f) ? d + log1pf(__expf(-d)) : log1pf(__expf(d));
        g_term[i] = term;
    }
}

// ---------------------------------------------------------------------------
// Kernel 4: deterministic final reduction -> scalar loss
// ---------------------------------------------------------------------------
__global__ void k_final(float* __restrict__ out) {
    __shared__ float sbs[BB];
    int wid = threadIdx.x >> 5, lane = threadIdx.x & 31;
    float s = 0.f;
    for (int r = lane; r < SLOTS_PER_B; r += 32) s += g_term[wid * SLOTS_PER_B + r];
    for (int o = 16; o > 0; o >>= 1) s += __shfl_xor_sync(0xffffffffu, s, o);
    if (lane == 0) sbs[wid] = s;
    __syncthreads();
    if (threadIdx.x == 0) {
        float tot = 0.f;
        for (int b = 0; b < BB; b++) {
            int pc = g_posCount[b]; if (pc < 1) pc = 1;
            tot += sbs[b] / (float)pc;
        }
        out[0] = tot / (float)BB;
    }
}

extern "C" void kernel_launch(void* const* d_in, const int* in_sizes, int n_in,
                              void* d_out, int out_size) {
    const float* f       = (const float*)d_in[0];   // (B,C,D)
    const float* p       = (const float*)d_in[1];   // (C,D)
    const int*   targets = (const int*)  d_in[2];   // (B,C)
    const float* rsc     = (const float*)d_in[3];   // (B,C)
    float* out = (float*)d_out;

    k_prep_p<<<CC, 256>>>(p);
    k_batch<<<BB, 256>>>(targets, rsc);
    k_norm_f<<<MAXP, 128>>>(f);
    k_gemm<<<dim3(MAXP / ATILE, CC / ETILE), 256>>>();
    k_select<<<MAXP, 256>>>(targets);
    k_final<<<1, 512>>>(out);
}

// round 3
// speedup vs baseline: 1.1364x; 1.1364x over previous
#include <cuda_runtime.h>
#include <math.h>

// Problem constants (fixed shapes from reference)
#define BB 16
#define CC 1024
#define DD 768
#define TAU_INV 10.0f
#define KHARD 306      // int((C-1)*0.3)
#define KRAND 717      // (C-1) - KHARD
#define SLOTS_PER_B 128
#define MAXP (BB * SLOTS_PER_B)   // 2048

// GEMM tiling
#define BM 64
#define BN 128
#define BKK 16
#define NCH (DD / BKK)            // 48

// Static device scratch (zero-initialized at module load; rows for unused
// slots are never written, so they stay 0 deterministically across replays).
__device__ float g_pnorm[CC * DD];
__device__ float g_F[MAXP * DD];
__device__ float g_S[MAXP * CC];
__device__ int   g_posList[MAXP];
__device__ int   g_posCount[BB];
__device__ unsigned char g_randFlag[BB * CC];
__device__ float g_term[MAXP];

__device__ __forceinline__ float neg_inf() { return __int_as_float(0xff800000); }

// order-preserving float<->uint key (monotone increasing)
__device__ __forceinline__ unsigned fkey(float f) {
    unsigned u = __float_as_uint(f);
    return (u & 0x80000000u) ? ~u : (u | 0x80000000u);
}
__device__ __forceinline__ float funkey(unsigned u) {
    return __uint_as_float((u & 0x80000000u) ? (u & 0x7fffffffu) : ~u);
}

#define FMA2(d, a, b, c) \
    asm("fma.rn.f32x2 %0, %1, %2, %3;" : "=l"(d) : "l"(a), "l"(b), "l"(c))

__device__ __forceinline__ unsigned long long pack2(float lo, float hi) {
    unsigned long long r;
    asm("mov.b64 %0, {%1, %2};" : "=l"(r)
        : "r"(__float_as_uint(lo)), "r"(__float_as_uint(hi)));
    return r;
}
__device__ __forceinline__ float lo2(unsigned long long v) {
    return __uint_as_float((unsigned)(v & 0xffffffffu));
}
__device__ __forceinline__ float hi2(unsigned long long v) {
    return __uint_as_float((unsigned)(v >> 32));
}

// ---------------------------------------------------------------------------
// Kernel 0 (fused): blocks [0,CC) normalize label_proto rows -> g_pnorm;
// blocks [CC, CC+BB) do per-batch positive compaction + exact random top-K.
// ---------------------------------------------------------------------------
__global__ void k_prep(const float* __restrict__ p,
                       const int* __restrict__ targets,
                       const float* __restrict__ rsc) {
    int tid = threadIdx.x;
    if (blockIdx.x < CC) {
        // ---- normalize one prototype row (float4) ----
        int e = blockIdx.x;
        const float4* row = (const float4*)(p + (size_t)e * DD);
        float4 v = make_float4(0.f, 0.f, 0.f, 0.f);
        float ss = 0.f;
        if (tid < DD / 4) {
            v = row[tid];
            ss = v.x * v.x + v.y * v.y + v.z * v.z + v.w * v.w;
        }
        for (int o = 16; o > 0; o >>= 1) ss += __shfl_xor_sync(0xffffffffu, ss, o);
        __shared__ float sW[8];
        __shared__ float sInv;
        if ((tid & 31) == 0) sW[tid >> 5] = ss;
        __syncthreads();
        if (tid == 0) {
            float t = 0.f;
            for (int w = 0; w < 8; w++) t += sW[w];
            sInv = 1.0f / fmaxf(sqrtf(t), 1e-12f);
        }
        __syncthreads();
        float inv = sInv;
        if (tid < DD / 4) {
            float4 o = make_float4(v.x * inv, v.y * inv, v.z * inv, v.w * inv);
            ((float4*)(g_pnorm + (size_t)e * DD))[tid] = o;
        }
        return;
    }

    // ---- per-batch: compaction + exact random top-KRAND ----
    int b = blockIdx.x - CC;
    __shared__ unsigned int skey[CC];
    __shared__ unsigned char sfl[CC];
    __shared__ int sW[8];
    __shared__ int sOut;

    int lane = tid & 31, wid = tid >> 5;
    int e0 = tid * 4;
    unsigned int key[4]; int posf[4]; int cnt = 0;
#pragma unroll
    for (int j = 0; j < 4; j++) {
        int e = e0 + j;
        int isPos = (targets[b * CC + e] != 0);
        posf[j] = isPos; cnt += isPos;
        // rand_scores in [0,1): float bits order-preserving as uint; +1 so
        // masked (positive) columns at key 0 are strictly below any real score.
        unsigned int k = isPos ? 0u : (__float_as_uint(rsc[b * CC + e]) + 1u);
        key[j] = k; skey[e] = k;
    }
    // exclusive prefix scan of positive counts (deterministic compaction)
    int inc = cnt;
    for (int o = 1; o < 32; o <<= 1) {
        int v = __shfl_up_sync(0xffffffffu, inc, o);
        if (lane >= o) inc += v;
    }
    if (lane == 31) sW[wid] = inc;
    __syncthreads();
    if (tid == 0) {
        int acc = 0;
        for (int w = 0; w < 8; w++) { int v = sW[w]; sW[w] = acc; acc += v; }
        g_posCount[b] = acc;
    }
    __syncthreads();
    int rank = sW[wid] + inc - cnt;
#pragma unroll
    for (int j = 0; j < 4; j++) {
        if (posf[j]) {
            if (rank < SLOTS_PER_B) g_posList[b * SLOTS_PER_B + rank] = e0 + j;
            rank++;
        }
    }
    __syncthreads();

    // binary search: largest V with count(key >= V) >= KRAND
    unsigned lo = 0u, hi = 0xFFFFFFFFu;
    while (hi - lo > 1u) {
        unsigned mid = lo + ((hi - lo) >> 1);
        int c4 = 0;
#pragma unroll
        for (int j = 0; j < 4; j++) c4 += (key[j] >= mid);
        c4 = __reduce_add_sync(0xffffffffu, c4);
        if (lane == 0) sW[wid] = c4;
        __syncthreads();
        int total = sW[0] + sW[1] + sW[2] + sW[3] + sW[4] + sW[5] + sW[6] + sW[7];
        if (total >= KRAND) lo = mid; else hi = mid;
        __syncthreads();
    }
    unsigned V = lo;
    int both4 = 0;
#pragma unroll
    for (int j = 0; j < 4; j++) both4 += (key[j] > V) * 2048 + (key[j] == V);
    both4 = __reduce_add_sync(0xffffffffu, both4);
    if (lane == 0) sW[wid] = both4;
    __syncthreads();
    if (tid == 0) { int t = 0; for (int w = 0; w < 8; w++) t += sW[w]; sOut = t; }
    __syncthreads();
    int n_gt = sOut / 2048;
    int n_eq = sOut % 2048;
    int rrem = KRAND - n_gt;   // >= 1 by construction

    if (n_eq == rrem) {
#pragma unroll
        for (int j = 0; j < 4; j++) sfl[e0 + j] = (key[j] >= V) ? 1 : 0;
        __syncthreads();
    } else {
        // rare: duplicates straddle the boundary -> lowest indices win
#pragma unroll
        for (int j = 0; j < 4; j++) sfl[e0 + j] = (key[j] > V) ? 1 : 0;
        __syncthreads();
        if (tid == 0) {
            int rem = rrem;
            for (int e = 0; e < CC && rem > 0; e++)
                if (skey[e] == V) { sfl[e] = 1; rem--; }
        }
        __syncthreads();
    }
#pragma unroll
    for (int j = 0; j < 4; j++) g_randFlag[b * CC + e0 + j] = sfl[e0 + j];
}

// ---------------------------------------------------------------------------
// Kernel 1: gather + normalize positive anchor features -> g_F (float4)
// ---------------------------------------------------------------------------
__global__ void k_norm_f(const float* __restrict__ f) {
    int i = blockIdx.x;
    int b = i >> 7, r = i & 127;
    int cnt = g_posCount[b]; if (cnt > SLOTS_PER_B) cnt = SLOTS_PER_B;
    if (r >= cnt) return;
    int c = g_posList[i];
    int tid = threadIdx.x;
    const float4* src = (const float4*)(f + (size_t)(b * CC + c) * DD);
    float4 v0 = src[tid];
    float4 v1 = make_float4(0.f, 0.f, 0.f, 0.f);
    float ss = v0.x * v0.x + v0.y * v0.y + v0.z * v0.z + v0.w * v0.w;
    if (tid < DD / 4 - 128) {
        v1 = src[tid + 128];
        ss += v1.x * v1.x + v1.y * v1.y + v1.z * v1.z + v1.w * v1.w;
    }
    for (int o = 16; o > 0; o >>= 1) ss += __shfl_xor_sync(0xffffffffu, ss, o);
    __shared__ float sW[4];
    __shared__ float sInv;
    if ((tid & 31) == 0) sW[tid >> 5] = ss;
    __syncthreads();
    if (tid == 0)
        sInv = 1.0f / fmaxf(sqrtf(sW[0] + sW[1] + sW[2] + sW[3]), 1e-12f);
    __syncthreads();
    float inv = sInv;
    float4* dst = (float4*)(g_F + (size_t)i * DD);
    dst[tid] = make_float4(v0.x * inv, v0.y * inv, v0.z * inv, v0.w * inv);
    if (tid < DD / 4 - 128)
        dst[tid + 128] = make_float4(v1.x * inv, v1.y * inv, v1.z * inv, v1.w * inv);
}

// ---------------------------------------------------------------------------
// Kernel 2: tiled fp32 GEMM with f32x2 packed FMA, double-buffered smem.
// S[slot][e] = dot(F[slot], Pn[e]).  grid (MAXP/BM=32, CC/BN=8), 256 thr.
// Thread tile 4(M) x 8(N); A broadcast via LDS.128, B pairs free via u64x2.
// ---------------------------------------------------------------------------
__global__ void __launch_bounds__(256, 2) k_gemm() {
    int aBase = blockIdx.x * BM;
    int batch = aBase >> 7;
    int cnt = g_posCount[batch]; if (cnt > SLOTS_PER_B) cnt = SLOTS_PER_B;
    int aOff = aBase & 127;
    if (aOff >= cnt) return;
    int eBase = blockIdx.y * BN;

    __shared__ float As[2][BKK][BM + 4];   // +4 pad: halve STS conflicts, keep 16B align
    __shared__ float Bs[2][BKK][BN + 4];

    int tid = threadIdx.x;
    int tx = tid & 15, ty = tid >> 4;
    int m0 = ty * 4, n0 = tx * 8;

    int rowA = tid >> 2, seg = tid & 3;
    const float4* gA  = (const float4*)(g_F     + (size_t)(aBase + rowA)      * DD) + seg;
    const float4* gB0 = (const float4*)(g_pnorm + (size_t)(eBase + rowA)      * DD) + seg;
    const float4* gB1 = (const float4*)(g_pnorm + (size_t)(eBase + 64 + rowA) * DD) + seg;

    float4 ra = gA[0], rb0 = gB0[0], rb1 = gB1[0];

    unsigned long long acc[4][4];
#pragma unroll
    for (int i = 0; i < 4; i++)
#pragma unroll
        for (int j = 0; j < 4; j++) acc[i][j] = 0ull;

    {
        const float* a = &ra.x; const float* b0 = &rb0.x; const float* b1 = &rb1.x;
#pragma unroll
        for (int i = 0; i < 4; i++) {
            As[0][seg * 4 + i][rowA]      = a[i];
            Bs[0][seg * 4 + i][rowA]      = b0[i];
            Bs[0][seg * 4 + i][rowA + 64] = b1[i];
        }
    }
    __syncthreads();

    for (int c = 0; c < NCH; c++) {
        int cur = c & 1;
        if (c + 1 < NCH) {
            ra  = gA[(c + 1) * 4];
            rb0 = gB0[(c + 1) * 4];
            rb1 = gB1[(c + 1) * 4];
        }
#pragma unroll
        for (int kk = 0; kk < BKK; kk++) {
            float4 av = *(const float4*)&As[cur][kk][m0];
            ulonglong2 bp0 = *(const ulonglong2*)&Bs[cur][kk][n0];      // pairs (n,n+1)
            ulonglong2 bp1 = *(const ulonglong2*)&Bs[cur][kk][n0 + 4];
            unsigned long long a2[4];
            a2[0] = pack2(av.x, av.x); a2[1] = pack2(av.y, av.y);
            a2[2] = pack2(av.z, av.z); a2[3] = pack2(av.w, av.w);
#pragma unroll
            for (int i = 0; i < 4; i++) {
                FMA2(acc[i][0], a2[i], bp0.x, acc[i][0]);
                FMA2(acc[i][1], a2[i], bp0.y, acc[i][1]);
                FMA2(acc[i][2], a2[i], bp1.x, acc[i][2]);
                FMA2(acc[i][3], a2[i], bp1.y, acc[i][3]);
            }
        }
        if (c + 1 < NCH) {
            int nxt = cur ^ 1;
            const float* a = &ra.x; const float* b0 = &rb0.x; const float* b1 = &rb1.x;
#pragma unroll
            for (int i = 0; i < 4; i++) {
                As[nxt][seg * 4 + i][rowA]      = a[i];
                Bs[nxt][seg * 4 + i][rowA]      = b0[i];
                Bs[nxt][seg * 4 + i][rowA + 64] = b1[i];
            }
        }
        __syncthreads();
    }

#pragma unroll
    for (int i = 0; i < 4; i++) {
        int slot = aBase + m0 + i;
        if (aOff + m0 + i < cnt) {
            float4 o0, o1;
            o0.x = lo2(acc[i][0]); o0.y = hi2(acc[i][0]);
            o0.z = lo2(acc[i][1]); o0.w = hi2(acc[i][1]);
            o1.x = lo2(acc[i][2]); o1.y = hi2(acc[i][2]);
            o1.z = lo2(acc[i][3]); o1.w = hi2(acc[i][3]);
            float* dst = g_S + (size_t)slot * CC + eBase + n0;
            *(float4*)dst = o0;
            *(float4*)(dst + 4) = o1;
        }
    }
}

// ---------------------------------------------------------------------------
// Kernel 3: per positive anchor: exact top-KHARD exp-sum via bit-threshold
// binary search (values only; ties exact), + random-set exp sum -> loss term.
// ---------------------------------------------------------------------------
__global__ void k_select(const int* __restrict__ targets) {
    int i = blockIdx.x;
    int b = i >> 7, r = i & 127;
    int cnt = g_posCount[b]; if (cnt > SLOTS_PER_B) cnt = SLOTS_PER_B;
    int tid = threadIdx.x;
    if (r >= cnt) { if (tid == 0) g_term[i] = 0.f; return; }
    int c = g_posList[i];

    __shared__ int sWi[8];
    __shared__ unsigned sWu[8];
    __shared__ float sWf[8];

    int lane = tid & 31, wid = tid >> 5;

    float4 s4 = *((const float4*)(g_S + (size_t)i * CC) + tid);
    int4   t4 = *((const int4*)(targets + b * CC) + tid);
    uchar4 r4 = *((const uchar4*)(g_randFlag + b * CC) + tid);
    float s[4] = {s4.x, s4.y, s4.z, s4.w};
    int neg[4] = {t4.x == 0, t4.y == 0, t4.z == 0, t4.w == 0};
    int fl[4]  = {r4.x, r4.y, r4.z, r4.w};
    unsigned key[4];
#pragma unroll
    for (int j = 0; j < 4; j++) key[j] = neg[j] ? fkey(s[j]) : 0u;

    // max over negatives (as key)
    unsigned mk = max(max(key[0], key[1]), max(key[2], key[3]));
    mk = __reduce_max_sync(0xffffffffu, mk);
    if (lane == 0) sWu[wid] = mk;
    __syncthreads();
    unsigned mAll = sWu[0];
#pragma unroll
    for (int w = 1; w < 8; w++) mAll = max(mAll, sWu[w]);
    float M = funkey(mAll);

    // binary search: largest T with count(key >= T) >= KHARD
    unsigned lo = 0u, hi = 0xffffffffu;
    while (hi - lo > 1u) {
        unsigned mid = lo + ((hi - lo) >> 1);
        int cm = (key[0] >= mid) + (key[1] >= mid) + (key[2] >= mid) + (key[3] >= mid);
        cm = __reduce_add_sync(0xffffffffu, cm);
        if (lane == 0) sWi[wid] = cm;
        __syncthreads();
        int tot = sWi[0] + sWi[1] + sWi[2] + sWi[3] + sWi[4] + sWi[5] + sWi[6] + sWi[7];
        if (tot >= KHARD) lo = mid; else hi = mid;
        __syncthreads();
    }
    unsigned T = lo;

    // strict-greater count + exp sums
    int g4 = (key[0] > T) + (key[1] > T) + (key[2] > T) + (key[3] > T);
    g4 = __reduce_add_sync(0xffffffffu, g4);
    if (lane == 0) sWi[wid] = g4;

    float es = 0.f;
#pragma unroll
    for (int j = 0; j < 4; j++) {
        float e = __expf((s[j] - M) * TAU_INV);
        if (key[j] > T) es += e;     // hard negatives above threshold
        if (fl[j])      es += e;     // random negatives (duplicates allowed, as ref)
    }
    for (int o = 16; o > 0; o >>= 1) es += __shfl_xor_sync(0xffffffffu, es, o);
    if (lane == 0) sWf[wid] = es;
    __syncthreads();

    if (tid == 0) {
        int n_gt = sWi[0] + sWi[1] + sWi[2] + sWi[3] + sWi[4] + sWi[5] + sWi[6] + sWi[7];
        float su = sWf[0] + sWf[1] + sWf[2] + sWf[3] + sWf[4] + sWf[5] + sWf[6] + sWf[7];
        int rem = KHARD - n_gt;                       // ties at the boundary
        su += (float)rem * __expf((funkey(T) - M) * TAU_INV);
        float pos = g_S[(size_t)i * CC + c] * TAU_INV;
        float lse = M * TAU_INV + __logf(su);
        float d = lse - pos;                           // logaddexp(pos,lse)-pos
        float term = (d > 0.f) ? d + log1pf(__expf(-d)) : log1pf(__expf(d));
        g_term[i] = term;
    }
}

// ---------------------------------------------------------------------------
// Kernel 4: deterministic final reduction -> scalar loss
// ---------------------------------------------------------------------------
__global__ void k_final(float* __restrict__ out) {
    __shared__ float sbs[BB];
    int wid = threadIdx.x >> 5, lane = threadIdx.x & 31;
    float s = 0.f;
    for (int r = lane; r < SLOTS_PER_B; r += 32) s += g_term[wid * SLOTS_PER_B + r];
    for (int o = 16; o > 0; o >>= 1) s += __shfl_xor_sync(0xffffffffu, s, o);
    if (lane == 0) sbs[wid] = s;
    __syncthreads();
    if (threadIdx.x == 0) {
        float tot = 0.f;
        for (int b = 0; b < BB; b++) {
            int pc = g_posCount[b]; if (pc < 1) pc = 1;
            tot += sbs[b] / (float)pc;
        }
        out[0] = tot / (float)BB;
    }
}

extern "C" void kernel_launch(void* const* d_in, const int* in_sizes, int n_in,
                              void* d_out, int out_size) {
    const float* f       = (const float*)d_in[0];   // (B,C,D)
    const float* p       = (const float*)d_in[1];   // (C,D)
    const int*   targets = (const int*)  d_in[2];   // (B,C)
    const float* rsc     = (const float*)d_in[3];   // (B,C)
    float* out = (float*)d_out;

    k_prep<<<CC + BB, 256>>>(p, targets, rsc);
    k_norm_f<<<MAXP, 128>>>(f);
    k_gemm<<<dim3(MAXP / BM, CC / BN), 256>>>();
    k_select<<<MAXP, 256>>>(targets);
    k_final<<<1, 512>>>(out);
}

// round 6
// speedup vs baseline: 2.4432x; 2.1500x over previous
#include <cuda_runtime.h>
#include <cuda_bf16.h>
#include <math.h>
#include <stdint.h>

// Problem constants
#define BB 16
#define CC 1024
#define DD 768
#define TAU_INV 10.0f
#define KHARD 306
#define KRAND 717
#define SLOTS_PER_B 128
#define MAXP (BB * SLOTS_PER_B)   // 2048

// Split-bf16 GEMM: K' = 3*DD = 2304 bf16 (A=[hi|hi|lo], B=[hi|lo|hi])
#define KP 2304
#define ROWB (KP * 2)             // 4608 bytes per row
#define KC 64                     // K columns per chunk (128 B)
#define NCHUNK (KP / KC)          // 36
#define TILE_BYTES (128 * 128)    // 16 KB per operand tile
#define DYN_SMEM (2 * 2 * TILE_BYTES)   // 64 KB (2 stages x A+B)

// Static device scratch (zero-init at load; unused slot rows never written)
__device__ __align__(128) unsigned char g_Ab[(size_t)MAXP * ROWB];   // 9.4 MB bf16
__device__ __align__(128) unsigned char g_Bb[(size_t)CC * ROWB];     // 4.7 MB bf16
__device__ float g_S[(size_t)MAXP * CC];
__device__ int   g_posList[MAXP];
__device__ int   g_posCount[BB];
__device__ unsigned char g_randFlag[BB * CC];
__device__ float g_term[MAXP];

// ---------------------------------------------------------------------------
// helpers
// ---------------------------------------------------------------------------
__device__ __forceinline__ uint32_t smem_u32(const void* p) {
    uint32_t a;
    asm("{ .reg .u64 t; cvta.to.shared.u64 t, %1; cvt.u32.u64 %0, t; }" : "=r"(a) : "l"(p));
    return a;
}
__device__ __forceinline__ void cp16(uint32_t dst, const void* src) {
    asm volatile("cp.async.ca.shared.global [%0], [%1], 16;" :: "r"(dst), "l"(src) : "memory");
}
__device__ __forceinline__ void ldsm_x4(uint32_t& r0, uint32_t& r1, uint32_t& r2, uint32_t& r3,
                                        uint32_t a) {
    asm volatile("ldmatrix.sync.aligned.m8n8.x4.shared.b16 {%0,%1,%2,%3}, [%4];"
                 : "=r"(r0), "=r"(r1), "=r"(r2), "=r"(r3) : "r"(a));
}
__device__ __forceinline__ void ldsm_x2(uint32_t& r0, uint32_t& r1, uint32_t a) {
    asm volatile("ldmatrix.sync.aligned.m8n8.x2.shared.b16 {%0,%1}, [%2];"
                 : "=r"(r0), "=r"(r1) : "r"(a));
}
__device__ __forceinline__ void mma16816(float* c, const uint32_t* a, const uint32_t* b) {
    asm volatile("mma.sync.aligned.m16n8k16.row.col.f32.bf16.bf16.f32 "
                 "{%0,%1,%2,%3}, {%4,%5,%6,%7}, {%8,%9}, {%0,%1,%2,%3};"
                 : "+f"(c[0]), "+f"(c[1]), "+f"(c[2]), "+f"(c[3])
                 : "r"(a[0]), "r"(a[1]), "r"(a[2]), "r"(a[3]), "r"(b[0]), "r"(b[1]));
}
// order-preserving float<->uint key
__device__ __forceinline__ unsigned fkey(float f) {
    unsigned u = __float_as_uint(f);
    return (u & 0x80000000u) ? ~u : (u | 0x80000000u);
}
__device__ __forceinline__ float funkey(unsigned u) {
    return __uint_as_float((u & 0x80000000u) ? (u & 0x7fffffffu) : ~u);
}

union BF8 { __nv_bfloat16 h[8]; uint4 u; };

// ---------------------------------------------------------------------------
// Kernel 0 (fused): blocks [0,CC): normalize proto row, split bf16 hi/lo,
// write g_Bb row [hi|lo|hi]. Blocks [CC,CC+BB): compaction + random top-K.
// ---------------------------------------------------------------------------
__global__ void k_prep(const float* __restrict__ p,
                       const int* __restrict__ targets,
                       const float* __restrict__ rsc) {
    int tid = threadIdx.x;
    if (blockIdx.x < CC) {
        int e = blockIdx.x;
        const float4* row = (const float4*)(p + (size_t)e * DD);
        float4 v0 = make_float4(0,0,0,0), v1 = make_float4(0,0,0,0);
        float ss = 0.f;
        if (tid < 96) {
            v0 = row[tid * 2]; v1 = row[tid * 2 + 1];
            ss = v0.x*v0.x + v0.y*v0.y + v0.z*v0.z + v0.w*v0.w
               + v1.x*v1.x + v1.y*v1.y + v1.z*v1.z + v1.w*v1.w;
        }
        for (int o = 16; o > 0; o >>= 1) ss += __shfl_xor_sync(0xffffffffu, ss, o);
        __shared__ float sW[8]; __shared__ float sInv;
        if ((tid & 31) == 0) sW[tid >> 5] = ss;
        __syncthreads();
        if (tid == 0) {
            float t = 0.f;
            for (int w = 0; w < 8; w++) t += sW[w];
            sInv = 1.0f / fmaxf(sqrtf(t), 1e-12f);
        }
        __syncthreads();
        if (tid < 96) {
            float inv = sInv;
            float v[8] = {v0.x*inv, v0.y*inv, v0.z*inv, v0.w*inv,
                          v1.x*inv, v1.y*inv, v1.z*inv, v1.w*inv};
            BF8 hi, lo;
#pragma unroll
            for (int j = 0; j < 8; j++) {
                hi.h[j] = __float2bfloat16(v[j]);
                lo.h[j] = __float2bfloat16(v[j] - __bfloat162float(hi.h[j]));
            }
            unsigned char* dst = g_Bb + (size_t)e * ROWB + tid * 16;
            *(uint4*)(dst)                = hi.u;   // seg0: hi
            *(uint4*)(dst + DD * 2)       = lo.u;   // seg1: lo
            *(uint4*)(dst + 2 * DD * 2)   = hi.u;   // seg2: hi
        }
        return;
    }

    // ---- per-batch compaction + exact random top-KRAND ----
    int b = blockIdx.x - CC;
    __shared__ unsigned int skey[CC];
    __shared__ unsigned char sfl[CC];
    __shared__ int sW[8];
    __shared__ int sOut;

    int lane = tid & 31, wid = tid >> 5;
    int e0 = tid * 4;
    unsigned int key[4]; int posf[4]; int cnt = 0;
#pragma unroll
    for (int j = 0; j < 4; j++) {
        int e = e0 + j;
        int isPos = (targets[b * CC + e] != 0);
        posf[j] = isPos; cnt += isPos;
        unsigned int k = isPos ? 0u : (__float_as_uint(rsc[b * CC + e]) + 1u);
        key[j] = k; skey[e] = k;
    }
    int inc = cnt;
    for (int o = 1; o < 32; o <<= 1) {
        int v = __shfl_up_sync(0xffffffffu, inc, o);
        if (lane >= o) inc += v;
    }
    if (lane == 31) sW[wid] = inc;
    __syncthreads();
    if (tid == 0) {
        int acc = 0;
        for (int w = 0; w < 8; w++) { int v = sW[w]; sW[w] = acc; acc += v; }
        g_posCount[b] = acc;
    }
    __syncthreads();
    int rank = sW[wid] + inc - cnt;
#pragma unroll
    for (int j = 0; j < 4; j++) {
        if (posf[j]) {
            if (rank < SLOTS_PER_B) g_posList[b * SLOTS_PER_B + rank] = e0 + j;
            rank++;
        }
    }
    __syncthreads();

    unsigned lo = 0u, hi = 0xFFFFFFFFu;
    while (hi - lo > 1u) {
        unsigned mid = lo + ((hi - lo) >> 1);
        int c4 = 0;
#pragma unroll
        for (int j = 0; j < 4; j++) c4 += (key[j] >= mid);
        c4 = __reduce_add_sync(0xffffffffu, c4);
        if (lane == 0) sW[wid] = c4;
        __syncthreads();
        int total = sW[0]+sW[1]+sW[2]+sW[3]+sW[4]+sW[5]+sW[6]+sW[7];
        if (total >= KRAND) lo = mid; else hi = mid;
        __syncthreads();
    }
    unsigned V = lo;
    int both4 = 0;
#pragma unroll
    for (int j = 0; j < 4; j++) both4 += (key[j] > V) * 2048 + (key[j] == V);
    both4 = __reduce_add_sync(0xffffffffu, both4);
    if (lane == 0) sW[wid] = both4;
    __syncthreads();
    if (tid == 0) { int t = 0; for (int w = 0; w < 8; w++) t += sW[w]; sOut = t; }
    __syncthreads();
    int n_gt = sOut / 2048;
    int n_eq = sOut % 2048;
    int rrem = KRAND - n_gt;

    if (n_eq == rrem) {
#pragma unroll
        for (int j = 0; j < 4; j++) sfl[e0 + j] = (key[j] >= V) ? 1 : 0;
        __syncthreads();
    } else {
#pragma unroll
        for (int j = 0; j < 4; j++) sfl[e0 + j] = (key[j] > V) ? 1 : 0;
        __syncthreads();
        if (tid == 0) {
            int rem = rrem;
            for (int e = 0; e < CC && rem > 0; e++)
                if (skey[e] == V) { sfl[e] = 1; rem--; }
        }
        __syncthreads();
    }
#pragma unroll
    for (int j = 0; j < 4; j++) g_randFlag[b * CC + e0 + j] = sfl[e0 + j];
}

// ---------------------------------------------------------------------------
// Kernel 1: gather + normalize positive anchor rows, split bf16 hi/lo,
// write g_Ab row [hi|hi|lo].
// ---------------------------------------------------------------------------
__global__ void k_norm_f(const float* __restrict__ f) {
    int i = blockIdx.x;
    int b = i >> 7, r = i & 127;
    int cnt = g_posCount[b]; if (cnt > SLOTS_PER_B) cnt = SLOTS_PER_B;
    if (r >= cnt) return;
    int c = g_posList[i];
    int tid = threadIdx.x;

    const float4* src = (const float4*)(f + (size_t)(b * CC + c) * DD);
    float4 v0 = make_float4(0,0,0,0), v1 = make_float4(0,0,0,0);
    float ss = 0.f;
    if (tid < 96) {
        v0 = src[tid * 2]; v1 = src[tid * 2 + 1];
        ss = v0.x*v0.x + v0.y*v0.y + v0.z*v0.z + v0.w*v0.w
           + v1.x*v1.x + v1.y*v1.y + v1.z*v1.z + v1.w*v1.w;
    }
    for (int o = 16; o > 0; o >>= 1) ss += __shfl_xor_sync(0xffffffffu, ss, o);
    __shared__ float sW[4]; __shared__ float sInv;
    if ((tid & 31) == 0) sW[tid >> 5] = ss;
    __syncthreads();
    if (tid == 0) sInv = 1.0f / fmaxf(sqrtf(sW[0]+sW[1]+sW[2]+sW[3]), 1e-12f);
    __syncthreads();
    if (tid >= 96) return;
    float inv = sInv;
    float v[8] = {v0.x*inv, v0.y*inv, v0.z*inv, v0.w*inv,
                  v1.x*inv, v1.y*inv, v1.z*inv, v1.w*inv};
    BF8 hi, lo;
#pragma unroll
    for (int j = 0; j < 8; j++) {
        hi.h[j] = __float2bfloat16(v[j]);
        lo.h[j] = __float2bfloat16(v[j] - __bfloat162float(hi.h[j]));
    }
    unsigned char* dst = g_Ab + (size_t)i * ROWB + tid * 16;
    *(uint4*)(dst)              = hi.u;   // seg0: hi
    *(uint4*)(dst + DD * 2)     = hi.u;   // seg1: hi
    *(uint4*)(dst + 2 * DD * 2) = lo.u;   // seg2: lo
}

// ---------------------------------------------------------------------------
// Kernel 2: bf16 tensor-core GEMM via mma.sync m16n8k16.
// Grid (16, 8): CTA = (batch, 128-proto tile). 256 thr = 8 warps, warp tile
// 64x32. Kc=64 chunks, double-buffered smem, cp.async, XOR-swizzled ldmatrix.
// ---------------------------------------------------------------------------
__global__ void __launch_bounds__(256, 1) k_gemm_mma() {
    extern __shared__ __align__(16) unsigned char dynsm[];
    int m = blockIdx.x;
    int cnt = g_posCount[m]; if (cnt <= 0) return;
    if (cnt > SLOTS_PER_B) cnt = SLOTS_PER_B;
    int eBase = blockIdx.y * 128;
    int tid = threadIdx.x, lane = tid & 31, wid = tid >> 5;
    int wm = (wid & 1) * 64, wn = (wid >> 1) * 32;

    uint32_t sbase = smem_u32(dynsm);
    const unsigned char* gA = g_Ab + (size_t)m * 128 * ROWB;
    const unsigned char* gB = g_Bb + (size_t)eBase * ROWB;

    float acc[4][4][4];
#pragma unroll
    for (int i = 0; i < 4; i++)
#pragma unroll
        for (int j = 0; j < 4; j++)
#pragma unroll
            for (int q = 0; q < 4; q++) acc[i][j][q] = 0.f;

    // copy chunk c into stage st (A tile + B tile, 16B swizzled segments)
    auto copy_chunk = [&](int c, int st) {
        uint32_t sA = sbase + st * (2 * TILE_BYTES);
        uint32_t sB = sA + TILE_BYTES;
#pragma unroll
        for (int i = 0; i < 4; i++) {
            int idx = tid + i * 256;
            int row = idx >> 3, seg = idx & 7;
            uint32_t so = (uint32_t)((row << 3) + (seg ^ (row & 7))) * 16;
            size_t go = (size_t)row * ROWB + c * 128 + seg * 16;
            cp16(sA + so, gA + go);
            cp16(sB + so, gB + go);
        }
        asm volatile("cp.async.commit_group;" ::: "memory");
    };

    copy_chunk(0, 0);
    for (int c = 0; c < NCHUNK; c++) {
        int cur = c & 1;
        if (c + 1 < NCHUNK) copy_chunk(c + 1, cur ^ 1);
        if (c + 1 < NCHUNK)
            asm volatile("cp.async.wait_group 1;" ::: "memory");
        else
            asm volatile("cp.async.wait_group 0;" ::: "memory");
        __syncthreads();

        uint32_t sA = sbase + cur * (2 * TILE_BYTES);
        uint32_t sB = sA + TILE_BYTES;
#pragma unroll
        for (int ks = 0; ks < 4; ks++) {
            uint32_t a[4][4], b[4][2];
#pragma unroll
            for (int mi = 0; mi < 4; mi++) {
                int row = wm + mi * 16 + (lane & 15);
                int kseg = 2 * ks + (lane >> 4);
                ldsm_x4(a[mi][0], a[mi][1], a[mi][2], a[mi][3],
                        sA + (uint32_t)((row << 3) + (kseg ^ (row & 7))) * 16);
            }
#pragma unroll
            for (int ni = 0; ni < 4; ni++) {
                int rn = wn + ni * 8 + (lane & 7);
                int kseg = 2 * ks + ((lane >> 3) & 1);
                ldsm_x2(b[ni][0], b[ni][1],
                        sB + (uint32_t)((rn << 3) + (kseg ^ (rn & 7))) * 16);
            }
#pragma unroll
            for (int mi = 0; mi < 4; mi++)
#pragma unroll
                for (int ni = 0; ni < 4; ni++)
                    mma16816(acc[mi][ni], a[mi], b[ni]);
        }
        __syncthreads();
    }

    // epilogue: D fragment rows qr/qr+8, cols qc,qc+1
    int qr = lane >> 2, qc = (lane & 3) * 2;
#pragma unroll
    for (int mi = 0; mi < 4; mi++) {
#pragma unroll
        for (int ni = 0; ni < 4; ni++) {
            int r0 = wm + mi * 16 + qr;
            int col = eBase + wn + ni * 8 + qc;
            if (r0 < cnt)
                *(float2*)(g_S + (size_t)(m * 128 + r0) * CC + col)
                    = make_float2(acc[mi][ni][0], acc[mi][ni][1]);
            if (r0 + 8 < cnt)
                *(float2*)(g_S + (size_t)(m * 128 + r0 + 8) * CC + col)
                    = make_float2(acc[mi][ni][2], acc[mi][ni][3]);
        }
    }
}

// ---------------------------------------------------------------------------
// Kernel 3: per positive anchor: exact top-KHARD exp-sum via bit-threshold
// binary search + random-set exp sum -> loss term.
// ---------------------------------------------------------------------------
__global__ void k_select(const int* __restrict__ targets) {
    int i = blockIdx.x;
    int b = i >> 7, r = i & 127;
    int cnt = g_posCount[b]; if (cnt > SLOTS_PER_B) cnt = SLOTS_PER_B;
    int tid = threadIdx.x;
    if (r >= cnt) { if (tid == 0) g_term[i] = 0.f; return; }
    int c = g_posList[i];

    __shared__ int sWi2[2][8];
    __shared__ unsigned sWmax[8];
    __shared__ unsigned sWmin[8];
    __shared__ int sWi[8];
    __shared__ float sWf[8];

    int lane = tid & 31, wid = tid >> 5;

    float4 s4 = *((const float4*)(g_S + (size_t)i * CC) + tid);
    int4   t4 = *((const int4*)(targets + b * CC) + tid);
    uchar4 r4 = *((const uchar4*)(g_randFlag + b * CC) + tid);
    float s[4] = {s4.x, s4.y, s4.z, s4.w};
    int neg[4] = {t4.x == 0, t4.y == 0, t4.z == 0, t4.w == 0};
    int fl[4]  = {r4.x, r4.y, r4.z, r4.w};
    unsigned key[4];
#pragma unroll
    for (int j = 0; j < 4; j++) key[j] = neg[j] ? fkey(s[j]) : 0u;

    unsigned mk = max(max(key[0], key[1]), max(key[2], key[3]));
    unsigned nk0 = neg[0] ? key[0] : 0xffffffffu;
    unsigned nk1 = neg[1] ? key[1] : 0xffffffffu;
    unsigned nk2 = neg[2] ? key[2] : 0xffffffffu;
    unsigned nk3 = neg[3] ? key[3] : 0xffffffffu;
    unsigned nk = min(min(nk0, nk1), min(nk2, nk3));
    mk = __reduce_max_sync(0xffffffffu, mk);
    nk = __reduce_min_sync(0xffffffffu, nk);
    if (lane == 0) { sWmax[wid] = mk; sWmin[wid] = nk; }
    __syncthreads();
    unsigned mAll = sWmax[0], nAll = sWmin[0];
#pragma unroll
    for (int w = 1; w < 8; w++) { mAll = max(mAll, sWmax[w]); nAll = min(nAll, sWmin[w]); }
    float M = funkey(mAll);

    unsigned lo = nAll, hi = mAll + 1u;
    int pb = 0;
    while (hi - lo > 1u) {
        unsigned mid = lo + ((hi - lo) >> 1);
        int cm = (key[0] >= mid) + (key[1] >= mid) + (key[2] >= mid) + (key[3] >= mid);
        cm = __reduce_add_sync(0xffffffffu, cm);
        if (lane == 0) sWi2[pb][wid] = cm;
        __syncthreads();
        int tot = sWi2[pb][0]+sWi2[pb][1]+sWi2[pb][2]+sWi2[pb][3]
                + sWi2[pb][4]+sWi2[pb][5]+sWi2[pb][6]+sWi2[pb][7];
        pb ^= 1;
        if (tot >= KHARD) lo = mid; else hi = mid;
    }
    unsigned T = lo;

    int g4 = (key[0] > T) + (key[1] > T) + (key[2] > T) + (key[3] > T);
    g4 = __reduce_add_sync(0xffffffffu, g4);
    if (lane == 0) sWi[wid] = g4;

    float es = 0.f;
#pragma unroll
    for (int j = 0; j < 4; j++) {
        float e = __expf((s[j] - M) * TAU_INV);
        if (key[j] > T) es += e;
        if (fl[j])      es += e;
    }
    for (int o = 16; o > 0; o >>= 1) es += __shfl_xor_sync(0xffffffffu, es, o);
    if (lane == 0) sWf[wid] = es;
    __syncthreads();

    if (tid == 0) {
        int n_gt = sWi[0]+sWi[1]+sWi[2]+sWi[3]+sWi[4]+sWi[5]+sWi[6]+sWi[7];
        float su = sWf[0]+sWf[1]+sWf[2]+sWf[3]+sWf[4]+sWf[5]+sWf[6]+sWf[7];
        int rem = KHARD - n_gt;
        su += (float)rem * __expf((funkey(T) - M) * TAU_INV);
        float pos = g_S[(size_t)i * CC + c] * TAU_INV;
        float lse = M * TAU_INV + __logf(su);
        float d = lse - pos;
        float term = (d > 0.f) ? d + log1pf(__expf(-d)) : log1pf(__expf(d));
        g_term[i] = term;
    }
}

// ---------------------------------------------------------------------------
// Kernel 4: deterministic final reduction -> scalar loss
// ---------------------------------------------------------------------------
__global__ void k_final(float* __restrict__ out) {
    __shared__ float sbs[BB];
    int wid = threadIdx.x >> 5, lane = threadIdx.x & 31;
    float s = 0.f;
    for (int r = lane; r < SLOTS_PER_B; r += 32) s += g_term[wid * SLOTS_PER_B + r];
    for (int o = 16; o > 0; o >>= 1) s += __shfl_xor_sync(0xffffffffu, s, o);
    if (lane == 0) sbs[wid] = s;
    __syncthreads();
    if (threadIdx.x == 0) {
        float tot = 0.f;
        for (int b = 0; b < BB; b++) {
            int pc = g_posCount[b]; if (pc < 1) pc = 1;
            tot += sbs[b] / (float)pc;
        }
        out[0] = tot / (float)BB;
    }
}

extern "C" void kernel_launch(void* const* d_in, const int* in_sizes, int n_in,
                              void* d_out, int out_size) {
    const float* f       = (const float*)d_in[0];   // (B,C,D)
    const float* p       = (const float*)d_in[1];   // (C,D)
    const int*   targets = (const int*)  d_in[2];   // (B,C)
    const float* rsc     = (const float*)d_in[3];   // (B,C)
    float* out = (float*)d_out;

    cudaFuncSetAttribute(k_gemm_mma, cudaFuncAttributeMaxDynamicSharedMemorySize, DYN_SMEM);

    k_prep<<<CC + BB, 256>>>(p, targets, rsc);
    k_norm_f<<<MAXP, 128>>>(f);
    k_gemm_mma<<<dim3(BB, CC / 128), 256, DYN_SMEM>>>();
    k_select<<<MAXP, 256>>>(targets);
    k_final<<<1, 512>>>(out);
}